// round 17
// baseline (speedup 1.0000x reference)
#include <cuda_runtime.h>
#include <cuda_fp16.h>
#include <math.h>

#define BN 8192
#define NN 100000
#define DD 8
#define KK 32
#define CC 100
#define TOTAL (BN + NN)
#define NTILES ((TOTAL + 127) / 128)   // 846
#define GRID_MLP 296                   // 2 blocks/SM persistent

#define KT   7            // k-tiles of 16 covering K=100 (pad 112)
#define MT2  7            // m-tiles of 16 covering M=100 (pad 112)
#define MT3  2            // m-tiles of 16 covering M=30  (pad 32)

#define NSH  68           // u32 words per point (136 fp16; 68 % 32 == 4 -> conflict-free B frags)

// ---- smem layout (bytes) ----
#define SM_H1    0                       // h1: 128 points * 68 u32 = 34816
#define SM_H2    34816                   // h2: 34816  (separate region)
#define SM_W2F   69632                   // W2 frags: 25088
#define SM_W3F   94720                   // W3 frags: 7168
#define SM_MISC  101888                  // mf floats [494]
#define SMEM_TOTAL 103936                // x2 blocks = 207.9K <= 228K per SM

// Feature scratch: [0..BN) queries, [BN..TOTAL) nodes, (x,y) pairs.
__device__ float g_feat[TOTAL * 2];

__device__ __forceinline__ unsigned h2pk(float lo, float hi) {  // u32 = {lo:lo, hi:hi}
    unsigned r;
    asm("cvt.rn.f16x2.f32 %0, %1, %2;" : "=r"(r) : "f"(hi), "f"(lo));
    return r;
}

__device__ __forceinline__ void mma16(float (&c)[4], const uint4& a, unsigned b0, unsigned b1) {
    asm("mma.sync.aligned.m16n8k16.row.col.f32.f16.f16.f32 "
        "{%0,%1,%2,%3}, {%4,%5,%6,%7}, {%8,%9}, {%0,%1,%2,%3};"
        : "+f"(c[0]), "+f"(c[1]), "+f"(c[2]), "+f"(c[3])
        : "r"(a.x), "r"(a.y), "r"(a.z), "r"(a.w), "r"(b0), "r"(b1));
}

// ---------------- persistent MLP kernel: 256 threads, 128 points per tile ----------------
// Tile loop is barrier-free across warps: each warp owns 16 points end-to-end.
__global__ __launch_bounds__(256, 2)
void mlp_kernel(const float* __restrict__ x, const float* __restrict__ nd,
                const float* __restrict__ W1, const float* __restrict__ b1,
                const float* __restrict__ W2, const float* __restrict__ b2,
                const float* __restrict__ W3, const float* __restrict__ b3,
                const float* __restrict__ W4, const float* __restrict__ b4)
{
    extern __shared__ char smraw[];
    unsigned* H1W = (unsigned*)(smraw + SM_H1);     // [point][kword] fp16x2
    unsigned* H2W = (unsigned*)(smraw + SM_H2);
    __half*   H2h = (__half*)(smraw + SM_H2);
    const uint4* W2F = (const uint4*)(smraw + SM_W2F);
    const uint4* W3F = (const uint4*)(smraw + SM_W3F);
    float* mf = (float*)(smraw + SM_MISC);

    const int tid = threadIdx.x;
    const int lane = tid & 31, warp = tid >> 5;
    const int g = lane >> 2, t = lane & 3;
    const int n0 = warp * 16;              // each warp owns 16 points (2 n-tiles of 8)

    // ---- phase 0: zero smem, inline coalesced pack of W2/W3, params (block-synced, once) ----
    {
        uint4* z = (uint4*)smraw;
        for (int i = tid; i < SM_MISC / 16; i += 256) z[i] = make_uint4(0, 0, 0, 0);
        __syncthreads();

        __half* W2Fh = (__half*)(smraw + SM_W2F);
        for (int i = tid; i < 2500; i += 256) {
            const float4 w = ((const float4*)W2)[i];
            const float we[4] = {w.x, w.y, w.z, w.w};
            const int base = i * 4;
            #pragma unroll
            for (int e = 0; e < 4; e++) {
                const int idx = base + e;
                const int row = idx / 100, col = idx - row * 100;
                const int mt = row >> 4, rr = row & 15;
                const int kt = col >> 4, cc = col & 15;
                const int ln = (rr & 7) * 4 + ((cc >> 1) & 3);
                const int r = (rr >> 3) + ((cc >> 3) << 1);
                const int fid = ((kt * MT2 + mt) * 32 + ln) * 4 + r;
                W2Fh[fid * 2 + (cc & 1)] = __float2half_rn(we[e]);
            }
        }
        __half* W3Fh = (__half*)(smraw + SM_W3F);
        for (int i = tid; i < 750; i += 256) {
            const float4 w = ((const float4*)W3)[i];
            const float we[4] = {w.x, w.y, w.z, w.w};
            const int base = i * 4;
            #pragma unroll
            for (int e = 0; e < 4; e++) {
                const int idx = base + e;
                const int row = idx / 100, col = idx - row * 100;
                const int mt = row >> 4, rr = row & 15;
                const int kt = col >> 4, cc = col & 15;
                const int ln = (rr & 7) * 4 + ((cc >> 1) & 3);
                const int r = (rr >> 3) + ((cc >> 3) << 1);
                const int fid = ((kt * MT3 + mt) * 32 + ln) * 4 + r;
                W3Fh[fid * 2 + (cc & 1)] = __float2half_rn(we[e]);
            }
        }
        for (int i = tid; i < 200; i += 256) mf[i] = W1[i];
        if (tid < 100) { mf[200 + tid] = b1[tid]; mf[300 + tid] = b2[tid]; }
        if (tid < 32)  mf[400 + tid] = (tid < 30) ? b3[tid] : 0.f;
        if (tid < 60)  mf[432 + tid] = W4[tid];
        if (tid < 2)   mf[492 + tid] = b4[tid];
    }
    __syncthreads();

#if __CUDA_ARCH__ >= 900
    // Allow the dependent route_kernel to launch now: it prefetches nbr_idx
    // (independent of g_feat) and then grid-syncs on our completion.
    cudaTriggerProgrammaticLaunchCompletion();
#endif

    for (int tile = blockIdx.x; tile < NTILES; tile += GRID_MLP) {
        const int pbase = tile * 128;

        // ---- layer 1: warp computes its OWN 16 points (lane = point x j-half) ----
        {
            const int p_loc = lane & 15, half = lane >> 4;
            const int p = n0 + p_loc;
            const int pg = pbase + p;
            float px = 0.f, py = 0.f;
            if (pg < TOTAL) {
                const float2 v = (pg < BN) ? ((const float2*)x)[pg]
                                           : ((const float2*)nd)[pg - BN];
                px = v.x; py = v.y;
            }
            const int j0 = half * 50;
            unsigned* dst = H1W + p * NSH + (j0 >> 1);
            #pragma unroll 5
            for (int j2 = 0; j2 < 25; j2++) {
                const int j = j0 + 2 * j2;
                const float v0 = fmaxf(fmaf(mf[2 * j], px,
                                       fmaf(mf[2 * j + 1], py, mf[200 + j])), 0.f);
                const float v1 = fmaxf(fmaf(mf[2 * j + 2], px,
                                       fmaf(mf[2 * j + 3], py, mf[201 + j])), 0.f);
                dst[j2] = h2pk(v0, v1);
            }
        }
        __syncwarp();   // H1 rows n0..n0+15 ready for this warp's B-frag reads

        // ---- layer 2: 100 -> 100 via fp16 mma reading own H1 rows ----
        float C[MT2][2][4];
        #pragma unroll
        for (int mt = 0; mt < MT2; mt++)
            #pragma unroll
            for (int nt = 0; nt < 2; nt++)
                #pragma unroll
                for (int r = 0; r < 4; r++) C[mt][nt][r] = 0.f;

        const unsigned* a0p = H1W + (n0 + g) * NSH + t;
        const unsigned* a1p = H1W + (n0 + 8 + g) * NSH + t;
        for (int kt = 0; kt < KT; kt++) {
            const int kw = kt * 8;
            unsigned bf[2][2];
            bf[0][0] = a0p[kw];     bf[0][1] = a0p[kw + 4];
            bf[1][0] = a1p[kw];     bf[1][1] = a1p[kw + 4];
            #pragma unroll
            for (int mt = 0; mt < MT2; mt++) {
                const uint4 a = W2F[(kt * MT2 + mt) * 32 + lane];
                mma16(C[mt][0], a, bf[0][0], bf[0][1]);
                mma16(C[mt][1], a, bf[1][0], bf[1][1]);
            }
        }

        // epilogue: h2 = relu(C + b2) -> own H2 rows (warp-internal)
        #pragma unroll
        for (int mt = 0; mt < MT2; mt++)
            #pragma unroll
            for (int half = 0; half < 2; half++) {
                const int row = mt * 16 + g + half * 8;
                const float bias = (row < 100) ? mf[300 + row] : 0.f;
                #pragma unroll
                for (int nt = 0; nt < 2; nt++) {
                    float v0 = C[mt][nt][2 * half + 0] + bias;
                    float v1 = C[mt][nt][2 * half + 1] + bias;
                    if (row >= 100) { v0 = 0.f; v1 = 0.f; }
                    else { v0 = fmaxf(v0, 0.f); v1 = fmaxf(v1, 0.f); }
                    const int p0 = n0 + nt * 8 + 2 * t;
                    H2h[p0 * (2 * NSH) + row] = __float2half_rn(v0);
                    H2h[(p0 + 1) * (2 * NSH) + row] = __float2half_rn(v1);
                }
            }
        __syncwarp();   // H2 rows n0..n0+15 ready

        // ---- layer 3: 100 -> 30 via fp16 mma reading own H2 rows ----
        float D[MT3][2][4];
        #pragma unroll
        for (int mt = 0; mt < MT3; mt++)
            #pragma unroll
            for (int nt = 0; nt < 2; nt++)
                #pragma unroll
                for (int r = 0; r < 4; r++) D[mt][nt][r] = 0.f;

        const unsigned* c0p = H2W + (n0 + g) * NSH + t;
        const unsigned* c1p = H2W + (n0 + 8 + g) * NSH + t;
        for (int kt = 0; kt < KT; kt++) {
            const int kw = kt * 8;
            unsigned bf[2][2];
            bf[0][0] = c0p[kw];     bf[0][1] = c0p[kw + 4];
            bf[1][0] = c1p[kw];     bf[1][1] = c1p[kw + 4];
            #pragma unroll
            for (int mt = 0; mt < MT3; mt++) {
                const uint4 a = W3F[(kt * MT3 + mt) * 32 + lane];
                mma16(D[mt][0], a, bf[0][0], bf[0][1]);
                mma16(D[mt][1], a, bf[1][0], bf[1][1]);
            }
        }

        // ---- layer 4: 30 -> 2 directly from D fragments, warp shuffle reduce ----
        {
            float acc[2][2][2];   // [nt][col01][out01]
            #pragma unroll
            for (int nt = 0; nt < 2; nt++)
                #pragma unroll
                for (int c2 = 0; c2 < 2; c2++) { acc[nt][c2][0] = 0.f; acc[nt][c2][1] = 0.f; }
            #pragma unroll
            for (int mt = 0; mt < MT3; mt++)
                #pragma unroll
                for (int half = 0; half < 2; half++) {
                    const int row = mt * 16 + g + half * 8;
                    const float w0 = (row < 30) ? mf[432 + row] : 0.f;   // W4[0][row]
                    const float w1 = (row < 30) ? mf[462 + row] : 0.f;   // W4[1][row]
                    const float bias = (row < 30) ? mf[400 + row] : 0.f;
                    #pragma unroll
                    for (int nt = 0; nt < 2; nt++) {
                        const float h0 = fmaxf(D[mt][nt][2 * half + 0] + bias, 0.f);
                        const float h1 = fmaxf(D[mt][nt][2 * half + 1] + bias, 0.f);
                        acc[nt][0][0] = fmaf(w0, h0, acc[nt][0][0]);
                        acc[nt][0][1] = fmaf(w1, h0, acc[nt][0][1]);
                        acc[nt][1][0] = fmaf(w0, h1, acc[nt][1][0]);
                        acc[nt][1][1] = fmaf(w1, h1, acc[nt][1][1]);
                    }
                }
            #pragma unroll
            for (int o = 4; o <= 16; o <<= 1)
                #pragma unroll
                for (int nt = 0; nt < 2; nt++)
                    #pragma unroll
                    for (int c2 = 0; c2 < 2; c2++) {
                        acc[nt][c2][0] += __shfl_xor_sync(0xffffffffu, acc[nt][c2][0], o);
                        acc[nt][c2][1] += __shfl_xor_sync(0xffffffffu, acc[nt][c2][1], o);
                    }
            if (g == 0) {   // lanes 0..3 hold final sums for their 4 point-columns
                #pragma unroll
                for (int nt = 0; nt < 2; nt++)
                    #pragma unroll
                    for (int c2 = 0; c2 < 2; c2++) {
                        const int pg = pbase + n0 + nt * 8 + 2 * t + c2;
                        if (pg < TOTAL)
                            ((float2*)g_feat)[pg] = make_float2(acc[nt][c2][0] + mf[492],
                                                                acc[nt][c2][1] + mf[493]);
                    }
            }
        }
        __syncwarp();   // all lanes' H1/H2 reads done before next tile's layer-1 writes
    }
}

// ---------------- routing kernel: FOUR queries per block, PDL prefetch ----------------
__global__ __launch_bounds__(256)
void route_kernel(const int* __restrict__ nbr_idx, const int* __restrict__ labels,
                  float* __restrict__ out)
{
    __shared__ float p_s[4][CC];
    __shared__ float terms[4][DD - 1];

    const int b0 = blockIdx.x * 4;
    const int tid = threadIdx.x;
    const int d = tid >> 5, lane = tid & 31;

    // only warp 7 (d == DD-1) touches p_s: it inits its own region, no block sync needed
    if (d == DD - 1) {
        for (int i = lane; i < 4 * CC; i += 32) ((float*)p_s)[i] = 0.f;
        __syncwarp();
    }

    // PREFETCH (independent of g_feat): all 4 index loads start before the grid sync.
    int idx4[4];
    #pragma unroll
    for (int u = 0; u < 4; u++) idx4[u] = nbr_idx[(b0 + u) * (DD * KK) + tid];

#if __CUDA_ARCH__ >= 900
    cudaGridDependencySynchronize();   // wait for mlp_kernel's g_feat to be complete+visible
#endif

    float2 q4[4], g4[4];
    #pragma unroll
    for (int u = 0; u < 4; u++) q4[u] = ((const float2*)g_feat)[b0 + u];
    #pragma unroll
    for (int u = 0; u < 4; u++) g4[u] = ((const float2*)g_feat)[BN + idx4[u]];

    float e4[4], s4[4];
    #pragma unroll
    for (int u = 0; u < 4; u++) {
        const float dx = g4[u].x - q4[u].x + 1e-6f;
        const float dy = g4[u].y - q4[u].y + 1e-6f;
        const float dist = sqrtf(fmaf(dx, dx, dy * dy));
        // dist >= 0 -> IEEE bits order-preserving: u32 redux.min == max(-dist)
        const float mind = __uint_as_float(__reduce_min_sync(0xffffffffu, __float_as_uint(dist)));
        e4[u] = __expf(mind - dist);   // argmax lane exactly exp(0) = 1
        s4[u] = e4[u];
    }
    #pragma unroll
    for (int o = 16; o > 0; o >>= 1)
        #pragma unroll
        for (int u = 0; u < 4; u++) s4[u] += __shfl_xor_sync(0xffffffffu, s4[u], o);

    if (d < DD - 1) {
        if (lane == 0) {
            #pragma unroll
            for (int u = 0; u < 4; u++)
                terms[u][d] = __logf(__fdividef(1.0f, s4[u]) + 1e-4f);
        }
    } else {
        #pragma unroll
        for (int u = 0; u < 4; u++) {
            const int c = labels[idx4[u]];
            atomicAdd(&p_s[u][c], __fdividef(e4[u], s4[u]));
        }
    }
    __syncthreads();

    for (int i = tid; i < 4 * CC; i += 256) {
        const int u = i / CC, c = i - u * CC;
        float tsum = terms[u][0] + terms[u][1] + terms[u][2] + terms[u][3]
                   + terms[u][4] + terms[u][5] + terms[u][6];
        out[(long)(b0 + u) * CC + c] = __logf(p_s[u][c] + 1e-4f) + tsum;
    }
}

extern "C" void kernel_launch(void* const* d_in, const int* in_sizes, int n_in,
                              void* d_out, int out_size)
{
    const float* x      = (const float*)d_in[0];
    const float* nd     = (const float*)d_in[1];
    const float* W1     = (const float*)d_in[2];
    const float* b1     = (const float*)d_in[3];
    const float* W2     = (const float*)d_in[4];
    const float* b2     = (const float*)d_in[5];
    const float* W3     = (const float*)d_in[6];
    const float* b3     = (const float*)d_in[7];
    const float* W4     = (const float*)d_in[8];
    const float* b4     = (const float*)d_in[9];
    const int*   labels = (const int*)d_in[10];
    const int*   nbr    = (const int*)d_in[11];
    float* out = (float*)d_out;

    cudaFuncSetAttribute(mlp_kernel, cudaFuncAttributeMaxDynamicSharedMemorySize, SMEM_TOTAL);

    mlp_kernel<<<GRID_MLP, 256, SMEM_TOTAL>>>(x, nd, W1, b1, W2, b2, W3, b3, W4, b4);

    // Programmatic dependent launch: route may launch while mlp runs; its
    // cudaGridDependencySynchronize() provides the ordering on g_feat.
    cudaLaunchConfig_t cfg = {};
    cfg.gridDim = dim3(BN / 4, 1, 1);
    cfg.blockDim = dim3(256, 1, 1);
    cfg.dynamicSmemBytes = 0;
    cfg.stream = 0;
    cudaLaunchAttribute attrs[1];
    attrs[0].id = cudaLaunchAttributeProgrammaticStreamSerialization;
    attrs[0].val.programmaticStreamSerializationAllowed = 1;
    cfg.attrs = attrs;
    cfg.numAttrs = 1;
    cudaLaunchKernelEx(&cfg, route_kernel, nbr, labels, out);
}